// round 16
// baseline (speedup 1.0000x reference)
#include <cuda_runtime.h>
#include <stdint.h>

#define Bc 32
#define Sc 128
#define Hc 128
#define BSH (Bc * Sc * Hc)

__device__ float g_M[BSH];
__device__ float g_Xt[BSH];                      // X transposed + tf32-rounded
__device__ float g_Wt[2 * 128 * 128 * 128];      // W1 tf32-rounded (16.8 MB)

// ---------------------------------------------------------------------------
__device__ __forceinline__ float gelu_f(float x) {
    return 0.5f * x * (1.0f + erff(x * 0.7071067811865476f));
}
__device__ __forceinline__ uint32_t s2u(const void* p) {
    uint32_t a;
    asm("{ .reg .u64 t; cvta.to.shared.u64 t, %1; cvt.u32.u64 %0, t; }" : "=r"(a) : "l"(p));
    return a;
}
__device__ __forceinline__ void cpasync16(uint32_t dst, const void* src) {
    asm volatile("cp.async.ca.shared.global [%0], [%1], 16;" :: "r"(dst), "l"(src));
}
#define CP_COMMIT() asm volatile("cp.async.commit_group;" ::: "memory")
#define CP_WAIT0()  asm volatile("cp.async.wait_group 0;" ::: "memory")
#define CP_WAIT1()  asm volatile("cp.async.wait_group 1;" ::: "memory")

__device__ __forceinline__ uint32_t f2tf32(float f) {
    uint32_t r;
    asm("cvt.rna.tf32.f32 %0, %1;" : "=r"(r) : "f"(f));
    return r;
}
__device__ __forceinline__ void mma_tf32(float* d, const uint32_t* a,
                                         const uint32_t* b) {
    asm volatile(
        "mma.sync.aligned.m16n8k8.row.col.f32.tf32.tf32.f32 "
        "{%0,%1,%2,%3}, {%4,%5,%6,%7}, {%8,%9}, {%0,%1,%2,%3};"
        : "+f"(d[0]), "+f"(d[1]), "+f"(d[2]), "+f"(d[3])
        : "r"(a[0]), "r"(a[1]), "r"(a[2]), "r"(a[3]), "r"(b[0]), "r"(b[1]));
}

// ---------------------------------------------------------------------------
// prep_w: round W1 (both scales) to tf32 in global
// ---------------------------------------------------------------------------
__global__ __launch_bounds__(256) void prep_w(const float* __restrict__ W1,
                                              float* __restrict__ Wt)
{
    int i = (blockIdx.x * blockDim.x + threadIdx.x) * 4;
    float4 v = *(const float4*)(W1 + i);
    v.x = __uint_as_float(f2tf32(v.x));
    v.y = __uint_as_float(f2tf32(v.y));
    v.z = __uint_as_float(f2tf32(v.z));
    v.w = __uint_as_float(f2tf32(v.w));
    *(float4*)(Wt + i) = v;
}

// ---------------------------------------------------------------------------
// xt: transpose X[b][s][h] -> Xt[b][h][s], tf32-rounded (one block per b)
// ---------------------------------------------------------------------------
__global__ __launch_bounds__(256) void xt_kernel(const float* __restrict__ X,
                                                 float* __restrict__ Xt)
{
    __shared__ float st[128][129];
    const int tid = threadIdx.x;
    const float* Xb = X + (size_t)blockIdx.x * 16384;
    float* Xtb = Xt + (size_t)blockIdx.x * 16384;
    for (int i = tid; i < 4096; i += 256) {
        int row = i >> 5, c4 = (i & 31) * 4;
        float4 v = *(const float4*)&Xb[row * 128 + c4];
        st[row][c4] = v.x; st[row][c4 + 1] = v.y;
        st[row][c4 + 2] = v.z; st[row][c4 + 3] = v.w;
    }
    __syncthreads();
    for (int i = tid; i < 4096; i += 256) {
        int h = i >> 5, s4 = (i & 31) * 4;
        float4 v = make_float4(
            __uint_as_float(f2tf32(st[s4][h])),
            __uint_as_float(f2tf32(st[s4 + 1][h])),
            __uint_as_float(f2tf32(st[s4 + 2][h])),
            __uint_as_float(f2tf32(st[s4 + 3][h])));
        *(float4*)&Xtb[h * 128 + s4] = v;
    }
}

// ---------------------------------------------------------------------------
// Mix kernel v8: tf32 mma, pre-converted operands, warp = (j, 64h, 16t),
// 3 CTAs/SM (acc = 32 floats). Class s: 16 j's x 2s slabs -> 4s blocks.
// ---------------------------------------------------------------------------
#define XSD 20
#define WSD 24

__global__ __launch_bounds__(256, 3) void mix_kernel(
    const float* __restrict__ Xt,    // [B,H,S] transposed tf32
    const float* __restrict__ Wt,    // [S,S,S] tf32 (this scale)
    const float* __restrict__ b1,    // [S,S]
    const float* __restrict__ W2,    // [S,S]
    float* __restrict__ out)         // [B,S,H], pre-initialized
{
    __shared__ __align__(16) float Xs[2][128 * XSD];      // 20 KB
    __shared__ __align__(16) float Ws[2][8 * 16 * WSD];   // 24 KB

    const int bx = blockIdx.x;
    const int b  = bx & 31;
    const int cb = bx >> 5;          // 0..143, descending s
    int s, cbase;
    if      (cb < 32)  { s = 8; cbase = 0;   }
    else if (cb < 60)  { s = 7; cbase = 32;  }
    else if (cb < 84)  { s = 6; cbase = 60;  }
    else if (cb < 104) { s = 5; cbase = 84;  }
    else if (cb < 120) { s = 4; cbase = 104; }
    else if (cb < 132) { s = 3; cbase = 120; }
    else if (cb < 140) { s = 2; cbase = 132; }
    else               { s = 1; cbase = 140; }
    const int blk = cb - cbase;      // [0, 4s)

    const int tid  = threadIdx.x;
    const int w    = tid >> 5;
    const int lane = tid & 31;
    const int r    = lane >> 2;
    const int q    = lane & 3;

    const int slab_id = blk * 8 + w;             // [0, 32s)
    const int jloc    = slab_id / (2 * s);
    const int rem     = slab_id - jloc * 2 * s;  // [0, 2s)
    const int tslab   = rem >> 1;
    const int mhalf   = rem & 1;
    const int j       = ((s - 1) << 4) + jloc;
    const int t0      = tslab << 4;
    const int m0      = mhalf << 6;

    const float* Xtb = Xt + (long)b * 16384;
    const uint32_t xsb = s2u(Xs), wsb = s2u(Ws);

    float d[4][2][4];
#pragma unroll
    for (int mt = 0; mt < 4; ++mt)
#pragma unroll
        for (int nt = 0; nt < 2; ++nt)
#pragma unroll
            for (int c = 0; c < 4; ++c) d[mt][nt][c] = 0.0f;

    auto issue = [&](int c, int buf) {
        const int k0 = c << 4;
#pragma unroll
        for (int p = 0; p < 2; ++p) {   // X: 512 lines
            int i = tid + p * 256;
            int row = i >> 2, q4 = (i & 3) * 4;
            cpasync16(xsb + (uint32_t)((buf * 128 * XSD) + row * XSD + q4) * 4,
                      Xtb + row * 128 + k0 + q4);
        }
#pragma unroll
        for (int p = 0; p < 2; ++p) {   // W: 512 lines (per-warp slab)
            int i = tid + p * 256;
            int lw = i >> 6, rem2 = i & 63;
            int kk = rem2 >> 2, q4 = (rem2 & 3) * 4;
            int sid = blk * 8 + lw;
            int jl = sid / (2 * s);
            int rm = sid - jl * 2 * s;
            int jj = ((s - 1) << 4) + jl;
            int tt = (rm >> 1) << 4;
            cpasync16(wsb + (uint32_t)((buf * 8 * 16 * WSD) +
                                       (lw * 16 + kk) * WSD + q4) * 4,
                      Wt + (long)jj * 16384 + (k0 + kk) * 128 + tt + q4);
        }
    };

    issue(0, 0);
    CP_COMMIT();
    if (s > 1) { issue(1, 1); CP_COMMIT(); }

    for (int c = 0; c < s; ++c) {
        if (c == s - 1) { CP_WAIT0(); } else { CP_WAIT1(); }
        __syncthreads();
        const int buf = c & 1;
        const float* Xc = &Xs[buf][m0 * XSD];
        const float* Wc = &Ws[buf][w * 16 * WSD];
#pragma unroll
        for (int kh = 0; kh < 2; ++kh) {
            uint32_t B[2][2];
#pragma unroll
            for (int nt = 0; nt < 2; ++nt) {
                B[nt][0] = __float_as_uint(Wc[(kh * 8 + q) * WSD + nt * 8 + r]);
                B[nt][1] = __float_as_uint(Wc[(kh * 8 + q + 4) * WSD + nt * 8 + r]);
            }
#pragma unroll
            for (int mt = 0; mt < 4; ++mt) {
                uint32_t A[4];
                A[0] = __float_as_uint(Xc[(mt * 16 + r) * XSD + kh * 8 + q]);
                A[1] = __float_as_uint(Xc[(mt * 16 + r + 8) * XSD + kh * 8 + q]);
                A[2] = __float_as_uint(Xc[(mt * 16 + r) * XSD + kh * 8 + q + 4]);
                A[3] = __float_as_uint(Xc[(mt * 16 + r + 8) * XSD + kh * 8 + q + 4]);
                mma_tf32(d[mt][0], A, B[0]);
                mma_tf32(d[mt][1], A, B[1]);
            }
        }
        __syncthreads();
        if (c + 2 < s) { issue(c + 2, buf); }
        CP_COMMIT();
    }

    // ---- epilogue: gelu*W2, reduce over t (quad shfl), atomicAdd ----
    float b1v[2][2], w2v[2][2];
#pragma unroll
    for (int nt = 0; nt < 2; ++nt)
#pragma unroll
        for (int cc = 0; cc < 2; ++cc) {
            int t = t0 + nt * 8 + 2 * q + cc;
            b1v[nt][cc] = b1[j * Sc + t];   // zero for t > j
            w2v[nt][cc] = W2[j * Sc + t];   // zero for t > j
        }

    float* o = out + ((long)b * Sc + j) * Hc + m0;
#pragma unroll
    for (int mt = 0; mt < 4; ++mt) {
        float p0 = 0.0f, p1 = 0.0f;
#pragma unroll
        for (int nt = 0; nt < 2; ++nt) {
            p0 += gelu_f(d[mt][nt][0] + b1v[nt][0]) * w2v[nt][0]
                + gelu_f(d[mt][nt][1] + b1v[nt][1]) * w2v[nt][1];
            p1 += gelu_f(d[mt][nt][2] + b1v[nt][0]) * w2v[nt][0]
                + gelu_f(d[mt][nt][3] + b1v[nt][1]) * w2v[nt][1];
        }
        p0 += __shfl_xor_sync(0xffffffffu, p0, 1);
        p0 += __shfl_xor_sync(0xffffffffu, p0, 2);
        p1 += __shfl_xor_sync(0xffffffffu, p1, 1);
        p1 += __shfl_xor_sync(0xffffffffu, p1, 2);
        if (q == 0) {
            atomicAdd(o + mt * 16 + r, p0);
            atomicAdd(o + mt * 16 + r + 8, p1);
        }
    }
}

// ---------------------------------------------------------------------------
// init: out[b,j,h] = base[b,j,h] + b2[j]
// ---------------------------------------------------------------------------
__global__ void init_kernel(const float4* __restrict__ base,
                            const float* __restrict__ b2,
                            float4* __restrict__ out)
{
    int i = blockIdx.x * blockDim.x + threadIdx.x;
    if (i < BSH / 4) {
        int j = (i >> 5) & 127;
        float bv = b2[j];
        float4 v = base[i];
        v.x += bv; v.y += bv; v.z += bv; v.w += bv;
        out[i] = v;
    }
}

// ---------------------------------------------------------------------------
// Fused MLP v3 (R15 measured win): tf32 mma, 128 blocks x 256 thr x 32 rows.
// ---------------------------------------------------------------------------
#define AS 132
#define MLP_SMEM_BYTES ((32 * AS + 32 * AS + 128 * AS + 128 * AS) * 4)

__global__ __launch_bounds__(256, 1) void mlp_fused(
    const float* __restrict__ in, const float* __restrict__ Wm1,
    const float* __restrict__ bm1, const float* __restrict__ Wm2,
    const float* __restrict__ bm2, float* __restrict__ out)
{
    extern __shared__ __align__(16) float sm[];
    float* As  = sm;                  // [32][AS]
    float* Mid = sm + 32 * AS;        // [32][AS]
    float* W1s = sm + 64 * AS;        // [128][AS]
    float* W2s = W1s + 128 * AS;      // [128][AS]

    const int tid  = threadIdx.x;
    const int w    = tid >> 5;
    const int lane = tid & 31;
    const int r    = lane >> 2;
    const int q    = lane & 3;
    const int mt   = w & 1;
    const int nq   = w >> 1;
    const int m0   = mt * 16;
    const int n0   = nq * 32;
    const int r0g  = blockIdx.x * 32;
    const uint32_t smb = s2u(sm);

    for (int i = tid; i < 32 * 32; i += 256) {
        int row = i >> 5, c4 = (i & 31) * 4;
        cpasync16(smb + (uint32_t)(row * AS + c4) * 4,
                  in + (r0g + row) * 128 + c4);
    }
    for (int i = tid; i < 128 * 32; i += 256) {
        int row = i >> 5, c4 = (i & 31) * 4;
        cpasync16(smb + (uint32_t)(64 * AS + row * AS + c4) * 4,
                  Wm1 + row * 128 + c4);
    }
    CP_COMMIT();
    for (int i = tid; i < 128 * 32; i += 256) {
        int row = i >> 5, c4 = (i & 31) * 4;
        cpasync16(smb + (uint32_t)(64 * AS + 128 * AS + row * AS + c4) * 4,
                  Wm2 + row * 128 + c4);
    }
    CP_COMMIT();

    CP_WAIT1();
    __syncthreads();

    // layer 1
    {
        float d[4][4];
#pragma unroll
        for (int nt = 0; nt < 4; ++nt)
#pragma unroll
            for (int c = 0; c < 4; ++c) d[nt][c] = 0.0f;
#pragma unroll
        for (int kh = 0; kh < 16; ++kh) {
            uint32_t A[4];
            A[0] = f2tf32(As[(m0 + r) * AS + kh * 8 + q]);
            A[1] = f2tf32(As[(m0 + r + 8) * AS + kh * 8 + q]);
            A[2] = f2tf32(As[(m0 + r) * AS + kh * 8 + q + 4]);
            A[3] = f2tf32(As[(m0 + r + 8) * AS + kh * 8 + q + 4]);
#pragma unroll
            for (int nt = 0; nt < 4; ++nt) {
                uint32_t B[2];
                B[0] = f2tf32(W1s[(kh * 8 + q) * AS + n0 + nt * 8 + r]);
                B[1] = f2tf32(W1s[(kh * 8 + q + 4) * AS + n0 + nt * 8 + r]);
                mma_tf32(d[nt], A, B);
            }
        }
#pragma unroll
        for (int nt = 0; nt < 4; ++nt) {
            int col = n0 + nt * 8 + 2 * q;
            float bb0 = bm1[col], bb1 = bm1[col + 1];
            Mid[(m0 + r) * AS + col]         = gelu_f(d[nt][0] + bb0);
            Mid[(m0 + r) * AS + col + 1]     = gelu_f(d[nt][1] + bb1);
            Mid[(m0 + r + 8) * AS + col]     = gelu_f(d[nt][2] + bb0);
            Mid[(m0 + r + 8) * AS + col + 1] = gelu_f(d[nt][3] + bb1);
        }
    }
    CP_WAIT0();
    __syncthreads();

    // layer 2
    {
        float d[4][4];
#pragma unroll
        for (int nt = 0; nt < 4; ++nt)
#pragma unroll
            for (int c = 0; c < 4; ++c) d[nt][c] = 0.0f;
#pragma unroll
        for (int kh = 0; kh < 16; ++kh) {
            uint32_t A[4];
            A[0] = f2tf32(Mid[(m0 + r) * AS + kh * 8 + q]);
            A[1] = f2tf32(Mid[(m0 + r + 8) * AS + kh * 8 + q]);
            A[2] = f2tf32(Mid[(m0 + r) * AS + kh * 8 + q + 4]);
            A[3] = f2tf32(Mid[(m0 + r + 8) * AS + kh * 8 + q + 4]);
#pragma unroll
            for (int nt = 0; nt < 4; ++nt) {
                uint32_t B[2];
                B[0] = f2tf32(W2s[(kh * 8 + q) * AS + n0 + nt * 8 + r]);
                B[1] = f2tf32(W2s[(kh * 8 + q + 4) * AS + n0 + nt * 8 + r]);
                mma_tf32(d[nt], A, B);
            }
        }
#pragma unroll
        for (int nt = 0; nt < 4; ++nt) {
            int col = n0 + nt * 8 + 2 * q;
            float bb0 = bm2[col], bb1 = bm2[col + 1];
            float* o0 = out + (r0g + m0 + r) * 128 + col;
            float* o1 = out + (r0g + m0 + r + 8) * 128 + col;
            o0[0] = d[nt][0] + bb0; o0[1] = d[nt][1] + bb1;
            o1[0] = d[nt][2] + bb0; o1[1] = d[nt][3] + bb1;
        }
    }
}

// ---------------------------------------------------------------------------
__global__ void copy_kernel(const float4* __restrict__ src,
                            float4* __restrict__ dst, int n4)
{
    int i = blockIdx.x * blockDim.x + threadIdx.x;
    if (i < n4) dst[i] = src[i];
}

// ---------------------------------------------------------------------------
extern "C" void kernel_launch(void* const* d_in, const int* in_sizes, int n_in,
                              void* d_out, int out_size)
{
    const float* trend0 = (const float*)d_in[0];
    const float* trend1 = (const float*)d_in[1];
    const float* trend2 = (const float*)d_in[2];
    const float* W1     = (const float*)d_in[3];
    const float* b1     = (const float*)d_in[4];
    const float* W2     = (const float*)d_in[5];
    const float* b2     = (const float*)d_in[6];
    const float* Wm1    = (const float*)d_in[7];
    const float* bm1    = (const float*)d_in[8];
    const float* Wm2    = (const float*)d_in[9];
    const float* bm2    = (const float*)d_in[10];

    float* out = (float*)d_out;
    float* O0 = out;             // mlp(trend0 + res1)
    float* O1 = out + BSH;       // mlp(trend1 + res0)
    float* O2 = out + 2 * BSH;   // trend2

    float *pM, *pXt, *pWt;
    cudaGetSymbolAddress((void**)&pM, g_M);
    cudaGetSymbolAddress((void**)&pXt, g_Xt);
    cudaGetSymbolAddress((void**)&pWt, g_Wt);

    cudaFuncSetAttribute(mlp_fused, cudaFuncAttributeMaxDynamicSharedMemorySize,
                         MLP_SMEM_BYTES);

    dim3 blk(256);
    dim3 mixGrid(144 * Bc);      // 4608 blocks, descending class size
    dim3 initGrid(BSH / 4 / 256);

    // one-time: tf32-round W1 (both scales)
    prep_w<<<4096, blk>>>(W1, pWt);

    // scale i=0: X = trend2, base = trend1 -> O1 = mlp(M0)
    xt_kernel<<<32, blk>>>(trend2, pXt);
    init_kernel<<<initGrid, blk>>>((const float4*)trend1, b2, (float4*)pM);
    mix_kernel<<<mixGrid, blk>>>(pXt, pWt, b1, W2, pM);
    mlp_fused<<<128, blk, MLP_SMEM_BYTES>>>(pM, Wm1, bm1, Wm2, bm2, O1);

    // scale i=1: X = O1, base = trend0 -> O0 = mlp(M1)
    xt_kernel<<<32, blk>>>(O1, pXt);
    init_kernel<<<initGrid, blk>>>((const float4*)trend0, b2 + Sc, (float4*)pM);
    mix_kernel<<<mixGrid, blk>>>(pXt, pWt + (long)128 * 16384,
                                 b1 + Sc * Sc, W2 + Sc * Sc, pM);
    mlp_fused<<<128, blk, MLP_SMEM_BYTES>>>(pM, Wm1, bm1, Wm2, bm2, O0);

    // out2 = trend2
    copy_kernel<<<BSH / 4 / 256, 256>>>((const float4*)trend2, (float4*)O2,
                                        BSH / 4);
}

// round 17
// speedup vs baseline: 1.1745x; 1.1745x over previous
#include <cuda_runtime.h>
#include <stdint.h>

#define Bc 32
#define Sc 128
#define Hc 128
#define BSH (Bc * Sc * Hc)

__device__ float g_M[BSH];
__device__ float g_Xt[BSH];                      // X transposed + tf32-rounded
__device__ float g_Wt[2 * 128 * 128 * 128];      // W1 tf32-rounded

// ---------------------------------------------------------------------------
__device__ __forceinline__ float gelu_f(float x) {
    return 0.5f * x * (1.0f + erff(x * 0.7071067811865476f));
}
__device__ __forceinline__ uint32_t s2u(const void* p) {
    uint32_t a;
    asm("{ .reg .u64 t; cvta.to.shared.u64 t, %1; cvt.u32.u64 %0, t; }" : "=r"(a) : "l"(p));
    return a;
}
__device__ __forceinline__ void cpasync16(uint32_t dst, const void* src) {
    asm volatile("cp.async.ca.shared.global [%0], [%1], 16;" :: "r"(dst), "l"(src));
}
#define CP_COMMIT() asm volatile("cp.async.commit_group;" ::: "memory")
#define CP_WAIT0()  asm volatile("cp.async.wait_group 0;" ::: "memory")
#define CP_WAIT1()  asm volatile("cp.async.wait_group 1;" ::: "memory")

__device__ __forceinline__ uint32_t f2tf32(float f) {
    uint32_t r;
    asm("cvt.rna.tf32.f32 %0, %1;" : "=r"(r) : "f"(f));
    return r;
}
__device__ __forceinline__ void mma_tf32(float* d, const uint32_t* a,
                                         const uint32_t* b) {
    asm volatile(
        "mma.sync.aligned.m16n8k8.row.col.f32.tf32.tf32.f32 "
        "{%0,%1,%2,%3}, {%4,%5,%6,%7}, {%8,%9}, {%0,%1,%2,%3};"
        : "+f"(d[0]), "+f"(d[1]), "+f"(d[2]), "+f"(d[3])
        : "r"(a[0]), "r"(a[1]), "r"(a[2]), "r"(a[3]), "r"(b[0]), "r"(b[1]));
}

// ---------------------------------------------------------------------------
// prep_w: round W1 (both scales) to tf32 in global
// ---------------------------------------------------------------------------
__global__ __launch_bounds__(256) void prep_w(const float* __restrict__ W1,
                                              float* __restrict__ Wt)
{
    int i = (blockIdx.x * blockDim.x + threadIdx.x) * 4;
    float4 v = *(const float4*)(W1 + i);
    v.x = __uint_as_float(f2tf32(v.x));
    v.y = __uint_as_float(f2tf32(v.y));
    v.z = __uint_as_float(f2tf32(v.z));
    v.w = __uint_as_float(f2tf32(v.w));
    *(float4*)(Wt + i) = v;
}

// ---------------------------------------------------------------------------
// xt: transpose X[b][s][h] -> Xt[b][h][s], tf32-rounded (one block per b)
// ---------------------------------------------------------------------------
__global__ __launch_bounds__(256) void xt_kernel(const float* __restrict__ X,
                                                 float* __restrict__ Xt)
{
    __shared__ float st[128][129];
    const int tid = threadIdx.x;
    const float* Xb = X + (size_t)blockIdx.x * 16384;
    float* Xtb = Xt + (size_t)blockIdx.x * 16384;
    for (int i = tid; i < 4096; i += 256) {
        int row = i >> 5, c4 = (i & 31) * 4;
        float4 v = *(const float4*)&Xb[row * 128 + c4];
        st[row][c4] = v.x; st[row][c4 + 1] = v.y;
        st[row][c4 + 2] = v.z; st[row][c4 + 3] = v.w;
    }
    __syncthreads();
    for (int i = tid; i < 4096; i += 256) {
        int h = i >> 5, s4 = (i & 31) * 4;
        float4 v = make_float4(
            __uint_as_float(f2tf32(st[s4][h])),
            __uint_as_float(f2tf32(st[s4 + 1][h])),
            __uint_as_float(f2tf32(st[s4 + 2][h])),
            __uint_as_float(f2tf32(st[s4 + 3][h])));
        *(float4*)&Xtb[h * 128 + s4] = v;
    }
}

// ---------------------------------------------------------------------------
// Mix kernel v9: R15 geometry (warp = (j, 128h x 16t), 2 CTA/SM, 72 classes)
// + pre-converted tf32 operands (no CVT in inner loop)
// + hoisted staging addresses (no div/mul in per-chunk issue).
// ---------------------------------------------------------------------------
#define XSD 20
#define WSD 24

__global__ __launch_bounds__(256, 2) void mix_kernel(
    const float* __restrict__ Xt,    // [B,H,S] transposed tf32
    const float* __restrict__ Wt,    // [S,S,S] tf32 (this scale)
    const float* __restrict__ b1,    // [S,S]
    const float* __restrict__ W2,    // [S,S]
    float* __restrict__ out)         // [B,S,H], pre-initialized
{
    __shared__ __align__(16) float Xs[2][128 * XSD];
    __shared__ __align__(16) float Ws[2][8 * 16 * WSD];

    const int bx = blockIdx.x;
    const int b  = bx & 31;
    const int cb = bx >> 5;
    int s, cbase;
    if      (cb < 16) { s = 8; cbase = 0;  }
    else if (cb < 30) { s = 7; cbase = 16; }
    else if (cb < 42) { s = 6; cbase = 30; }
    else if (cb < 52) { s = 5; cbase = 42; }
    else if (cb < 60) { s = 4; cbase = 52; }
    else if (cb < 66) { s = 3; cbase = 60; }
    else if (cb < 70) { s = 2; cbase = 66; }
    else              { s = 1; cbase = 70; }
    const int blk8 = cb - cbase;

    const int tid  = threadIdx.x;
    const int w    = tid >> 5;
    const int lane = tid & 31;
    const int r    = lane >> 2;
    const int q    = lane & 3;

    const int slab_id = blk8 * 8 + w;
    const int jloc    = slab_id / s;
    const int slabl   = slab_id - jloc * s;
    const int j       = ((s - 1) << 4) + jloc;
    const int t0      = slabl << 4;

    const float* Xtb = Xt + (long)b * 16384;
    const uint32_t xsb = s2u(Xs), wsb = s2u(Ws);

    // ---- hoisted staging addresses (computed once) ----
    const float* xsrc[2];
    const float* wsrc[2];
    uint32_t xdst[2], wdst[2];
#pragma unroll
    for (int p = 0; p < 2; ++p) {
        int i = tid + p * 256;
        // X line
        int xrow = i >> 2, xq4 = (i & 3) * 4;
        xsrc[p] = Xtb + xrow * 128 + xq4;
        xdst[p] = (uint32_t)(xrow * XSD + xq4) * 4;
        // W line
        int lw = i >> 6, rem = i & 63;
        int kk = rem >> 2, wq4 = (rem & 3) * 4;
        int sid = blk8 * 8 + lw;
        int jl = sid / s;
        int jj = ((s - 1) << 4) + jl;
        int tt = (sid - jl * s) << 4;
        wsrc[p] = Wt + (long)jj * 16384 + kk * 128 + tt + wq4;
        wdst[p] = (uint32_t)((lw * 16 + kk) * WSD + wq4) * 4;
    }

    auto issue = [&](int c, int buf) {
        const uint32_t xo = xsb + (uint32_t)buf * (128 * XSD * 4);
        const uint32_t wo = wsb + (uint32_t)buf * (8 * 16 * WSD * 4);
        const int ks = c * 16;
        cpasync16(xo + xdst[0], xsrc[0] + ks);
        cpasync16(xo + xdst[1], xsrc[1] + ks);
        cpasync16(wo + wdst[0], wsrc[0] + ks * 128);
        cpasync16(wo + wdst[1], wsrc[1] + ks * 128);
    };

    float d[8][2][4];
#pragma unroll
    for (int mt = 0; mt < 8; ++mt)
#pragma unroll
        for (int nt = 0; nt < 2; ++nt)
#pragma unroll
            for (int c = 0; c < 4; ++c) d[mt][nt][c] = 0.0f;

    issue(0, 0);
    CP_COMMIT();
    if (s > 1) { issue(1, 1); CP_COMMIT(); }

    for (int c = 0; c < s; ++c) {
        if (c == s - 1) { CP_WAIT0(); } else { CP_WAIT1(); }
        __syncthreads();
        const int buf = c & 1;
        const float* Xc = &Xs[buf][0];
        const float* Wc = &Ws[buf][w * 16 * WSD];
#pragma unroll
        for (int kh = 0; kh < 2; ++kh) {
            uint32_t B[2][2];
#pragma unroll
            for (int nt = 0; nt < 2; ++nt) {
                B[nt][0] = __float_as_uint(Wc[(kh * 8 + q) * WSD + nt * 8 + r]);
                B[nt][1] = __float_as_uint(Wc[(kh * 8 + q + 4) * WSD + nt * 8 + r]);
            }
#pragma unroll
            for (int mt = 0; mt < 8; ++mt) {
                uint32_t A[4];
                A[0] = __float_as_uint(Xc[(mt * 16 + r) * XSD + kh * 8 + q]);
                A[1] = __float_as_uint(Xc[(mt * 16 + r + 8) * XSD + kh * 8 + q]);
                A[2] = __float_as_uint(Xc[(mt * 16 + r) * XSD + kh * 8 + q + 4]);
                A[3] = __float_as_uint(Xc[(mt * 16 + r + 8) * XSD + kh * 8 + q + 4]);
                mma_tf32(d[mt][0], A, B[0]);
                mma_tf32(d[mt][1], A, B[1]);
            }
        }
        __syncthreads();
        if (c + 2 < s) { issue(c + 2, buf); }
        CP_COMMIT();
    }

    // ---- epilogue: gelu*W2, reduce over t (quad shfl), atomicAdd ----
    float b1v[2][2], w2v[2][2];
#pragma unroll
    for (int nt = 0; nt < 2; ++nt)
#pragma unroll
        for (int cc = 0; cc < 2; ++cc) {
            int t = t0 + nt * 8 + 2 * q + cc;
            b1v[nt][cc] = b1[j * Sc + t];
            w2v[nt][cc] = W2[j * Sc + t];
        }

    float* o = out + ((long)b * Sc + j) * Hc;
#pragma unroll
    for (int mt = 0; mt < 8; ++mt) {
        float p0 = 0.0f, p1 = 0.0f;
#pragma unroll
        for (int nt = 0; nt < 2; ++nt) {
            p0 += gelu_f(d[mt][nt][0] + b1v[nt][0]) * w2v[nt][0]
                + gelu_f(d[mt][nt][1] + b1v[nt][1]) * w2v[nt][1];
            p1 += gelu_f(d[mt][nt][2] + b1v[nt][0]) * w2v[nt][0]
                + gelu_f(d[mt][nt][3] + b1v[nt][1]) * w2v[nt][1];
        }
        p0 += __shfl_xor_sync(0xffffffffu, p0, 1);
        p0 += __shfl_xor_sync(0xffffffffu, p0, 2);
        p1 += __shfl_xor_sync(0xffffffffu, p1, 1);
        p1 += __shfl_xor_sync(0xffffffffu, p1, 2);
        if (q == 0) {
            atomicAdd(o + mt * 16 + r, p0);
            atomicAdd(o + mt * 16 + r + 8, p1);
        }
    }
}

// ---------------------------------------------------------------------------
// init: out[b,j,h] = base[b,j,h] + b2[j]
// ---------------------------------------------------------------------------
__global__ void init_kernel(const float4* __restrict__ base,
                            const float* __restrict__ b2,
                            float4* __restrict__ out)
{
    int i = blockIdx.x * blockDim.x + threadIdx.x;
    if (i < BSH / 4) {
        int j = (i >> 5) & 127;
        float bv = b2[j];
        float4 v = base[i];
        v.x += bv; v.y += bv; v.z += bv; v.w += bv;
        out[i] = v;
    }
}

// ---------------------------------------------------------------------------
// Fused MLP v3 (R15 measured win): tf32 mma, 128 blocks x 256 thr x 32 rows.
// ---------------------------------------------------------------------------
#define AS 132
#define MLP_SMEM_BYTES ((32 * AS + 32 * AS + 128 * AS + 128 * AS) * 4)

__global__ __launch_bounds__(256, 1) void mlp_fused(
    const float* __restrict__ in, const float* __restrict__ Wm1,
    const float* __restrict__ bm1, const float* __restrict__ Wm2,
    const float* __restrict__ bm2, float* __restrict__ out)
{
    extern __shared__ __align__(16) float sm[];
    float* As  = sm;                  // [32][AS]
    float* Mid = sm + 32 * AS;        // [32][AS]
    float* W1s = sm + 64 * AS;        // [128][AS]
    float* W2s = W1s + 128 * AS;      // [128][AS]

    const int tid  = threadIdx.x;
    const int w    = tid >> 5;
    const int lane = tid & 31;
    const int r    = lane >> 2;
    const int q    = lane & 3;
    const int mt   = w & 1;
    const int nq   = w >> 1;
    const int m0   = mt * 16;
    const int n0   = nq * 32;
    const int r0g  = blockIdx.x * 32;
    const uint32_t smb = s2u(sm);

    for (int i = tid; i < 32 * 32; i += 256) {
        int row = i >> 5, c4 = (i & 31) * 4;
        cpasync16(smb + (uint32_t)(row * AS + c4) * 4,
                  in + (r0g + row) * 128 + c4);
    }
    for (int i = tid; i < 128 * 32; i += 256) {
        int row = i >> 5, c4 = (i & 31) * 4;
        cpasync16(smb + (uint32_t)(64 * AS + row * AS + c4) * 4,
                  Wm1 + row * 128 + c4);
    }
    CP_COMMIT();
    for (int i = tid; i < 128 * 32; i += 256) {
        int row = i >> 5, c4 = (i & 31) * 4;
        cpasync16(smb + (uint32_t)(64 * AS + 128 * AS + row * AS + c4) * 4,
                  Wm2 + row * 128 + c4);
    }
    CP_COMMIT();

    CP_WAIT1();
    __syncthreads();

    // layer 1
    {
        float d[4][4];
#pragma unroll
        for (int nt = 0; nt < 4; ++nt)
#pragma unroll
            for (int c = 0; c < 4; ++c) d[nt][c] = 0.0f;
#pragma unroll
        for (int kh = 0; kh < 16; ++kh) {
            uint32_t A[4];
            A[0] = f2tf32(As[(m0 + r) * AS + kh * 8 + q]);
            A[1] = f2tf32(As[(m0 + r + 8) * AS + kh * 8 + q]);
            A[2] = f2tf32(As[(m0 + r) * AS + kh * 8 + q + 4]);
            A[3] = f2tf32(As[(m0 + r + 8) * AS + kh * 8 + q + 4]);
#pragma unroll
            for (int nt = 0; nt < 4; ++nt) {
                uint32_t B[2];
                B[0] = f2tf32(W1s[(kh * 8 + q) * AS + n0 + nt * 8 + r]);
                B[1] = f2tf32(W1s[(kh * 8 + q + 4) * AS + n0 + nt * 8 + r]);
                mma_tf32(d[nt], A, B);
            }
        }
#pragma unroll
        for (int nt = 0; nt < 4; ++nt) {
            int col = n0 + nt * 8 + 2 * q;
            float bb0 = bm1[col], bb1 = bm1[col + 1];
            Mid[(m0 + r) * AS + col]         = gelu_f(d[nt][0] + bb0);
            Mid[(m0 + r) * AS + col + 1]     = gelu_f(d[nt][1] + bb1);
            Mid[(m0 + r + 8) * AS + col]     = gelu_f(d[nt][2] + bb0);
            Mid[(m0 + r + 8) * AS + col + 1] = gelu_f(d[nt][3] + bb1);
        }
    }
    CP_WAIT0();
    __syncthreads();

    // layer 2
    {
        float d[4][4];
#pragma unroll
        for (int nt = 0; nt < 4; ++nt)
#pragma unroll
            for (int c = 0; c < 4; ++c) d[nt][c] = 0.0f;
#pragma unroll
        for (int kh = 0; kh < 16; ++kh) {
            uint32_t A[4];
            A[0] = f2tf32(Mid[(m0 + r) * AS + kh * 8 + q]);
            A[1] = f2tf32(Mid[(m0 + r + 8) * AS + kh * 8 + q]);
            A[2] = f2tf32(Mid[(m0 + r) * AS + kh * 8 + q + 4]);
            A[3] = f2tf32(Mid[(m0 + r + 8) * AS + kh * 8 + q + 4]);
#pragma unroll
            for (int nt = 0; nt < 4; ++nt) {
                uint32_t B[2];
                B[0] = f2tf32(W2s[(kh * 8 + q) * AS + n0 + nt * 8 + r]);
                B[1] = f2tf32(W2s[(kh * 8 + q + 4) * AS + n0 + nt * 8 + r]);
                mma_tf32(d[nt], A, B);
            }
        }
#pragma unroll
        for (int nt = 0; nt < 4; ++nt) {
            int col = n0 + nt * 8 + 2 * q;
            float bb0 = bm2[col], bb1 = bm2[col + 1];
            float* o0 = out + (r0g + m0 + r) * 128 + col;
            float* o1 = out + (r0g + m0 + r + 8) * 128 + col;
            o0[0] = d[nt][0] + bb0; o0[1] = d[nt][1] + bb1;
            o1[0] = d[nt][2] + bb0; o1[1] = d[nt][3] + bb1;
        }
    }
}

// ---------------------------------------------------------------------------
__global__ void copy_kernel(const float4* __restrict__ src,
                            float4* __restrict__ dst, int n4)
{
    int i = blockIdx.x * blockDim.x + threadIdx.x;
    if (i < n4) dst[i] = src[i];
}

// ---------------------------------------------------------------------------
extern "C" void kernel_launch(void* const* d_in, const int* in_sizes, int n_in,
                              void* d_out, int out_size)
{
    const float* trend0 = (const float*)d_in[0];
    const float* trend1 = (const float*)d_in[1];
    const float* trend2 = (const float*)d_in[2];
    const float* W1     = (const float*)d_in[3];
    const float* b1     = (const float*)d_in[4];
    const float* W2     = (const float*)d_in[5];
    const float* b2     = (const float*)d_in[6];
    const float* Wm1    = (const float*)d_in[7];
    const float* bm1    = (const float*)d_in[8];
    const float* Wm2    = (const float*)d_in[9];
    const float* bm2    = (const float*)d_in[10];

    float* out = (float*)d_out;
    float* O0 = out;             // mlp(trend0 + res1)
    float* O1 = out + BSH;       // mlp(trend1 + res0)
    float* O2 = out + 2 * BSH;   // trend2

    float *pM, *pXt, *pWt;
    cudaGetSymbolAddress((void**)&pM, g_M);
    cudaGetSymbolAddress((void**)&pXt, g_Xt);
    cudaGetSymbolAddress((void**)&pWt, g_Wt);

    cudaFuncSetAttribute(mlp_fused, cudaFuncAttributeMaxDynamicSharedMemorySize,
                         MLP_SMEM_BYTES);

    dim3 blk(256);
    dim3 mixGrid(72 * Bc);       // 2304 blocks, descending class size
    dim3 initGrid(BSH / 4 / 256);

    // one-time: tf32-round W1 (both scales)
    prep_w<<<4096, blk>>>(W1, pWt);

    // scale i=0: X = trend2, base = trend1 -> O1 = mlp(M0)
    xt_kernel<<<32, blk>>>(trend2, pXt);
    init_kernel<<<initGrid, blk>>>((const float4*)trend1, b2, (float4*)pM);
    mix_kernel<<<mixGrid, blk>>>(pXt, pWt, b1, W2, pM);
    mlp_fused<<<128, blk, MLP_SMEM_BYTES>>>(pM, Wm1, bm1, Wm2, bm2, O1);

    // scale i=1: X = O1, base = trend0 -> O0 = mlp(M1)
    xt_kernel<<<32, blk>>>(O1, pXt);
    init_kernel<<<initGrid, blk>>>((const float4*)trend0, b2 + Sc, (float4*)pM);
    mix_kernel<<<mixGrid, blk>>>(pXt, pWt + (long)128 * 16384,
                                 b1 + Sc * Sc, W2 + Sc * Sc, pM);
    mlp_fused<<<128, blk, MLP_SMEM_BYTES>>>(pM, Wm1, bm1, Wm2, bm2, O0);

    // out2 = trend2
    copy_kernel<<<BSH / 4 / 256, 256>>>((const float4*)trend2, (float4*)O2,
                                        BSH / 4);
}